// round 1
// baseline (speedup 1.0000x reference)
#include <cuda_runtime.h>

// ThinVesselLoss: the EDT in the reference only matters through
// thin = (0 < 2*dist < 3)  <=>  D2 in {1,2}  <=>  foreground pixel with at
// least one 8-neighbor background pixel (in-bounds). So the whole loss is a
// 3x3 stencil on (target > 0.5) plus weighted BCE, reduced to a scalar mean.

#define B_N 4
#define H_N 512
#define W_N 512
#define NPIX (B_N * H_N * W_N)          // 1048576
#define WARPS_PER_BLOCK 8
#define NBLOCKS ((B_N * H_N) / WARPS_PER_BLOCK)  // 2048 warps / 8 = 256 blocks

__device__ float g_partial[NBLOCKS];

// One warp per image row: 32 lanes x 16 pixels = 512 columns.
__global__ void __launch_bounds__(WARPS_PER_BLOCK * 32)
tv_main(const float* __restrict__ pred, const float* __restrict__ tgt) {
    const int warp_in_blk = threadIdx.x >> 5;
    const int lane        = threadIdx.x & 31;
    const int w           = blockIdx.x * WARPS_PER_BLOCK + warp_in_blk; // 0..2047
    const int b           = w >> 9;        // / H_N
    const int y           = w & (H_N - 1); // % H_N
    const long base = ((long)b * H_N + y) * W_N + lane * 16;

    // ---- Pass 1: load target rows, build per-lane 16-bit background masks ----
    float ct[16];
    unsigned mC = 0u, mA = 0u, mB = 0u;

    const float4* c4 = reinterpret_cast<const float4*>(tgt + base);
#pragma unroll
    for (int ch = 0; ch < 4; ch++) {
        float4 v = __ldg(c4 + ch);
        ct[4 * ch + 0] = v.x; ct[4 * ch + 1] = v.y;
        ct[4 * ch + 2] = v.z; ct[4 * ch + 3] = v.w;
        mC |= (unsigned)(v.x <= 0.5f) << (4 * ch + 0);
        mC |= (unsigned)(v.y <= 0.5f) << (4 * ch + 1);
        mC |= (unsigned)(v.z <= 0.5f) << (4 * ch + 2);
        mC |= (unsigned)(v.w <= 0.5f) << (4 * ch + 3);
    }
    if (y > 0) {
        const float4* a4 = reinterpret_cast<const float4*>(tgt + base - W_N);
#pragma unroll
        for (int ch = 0; ch < 4; ch++) {
            float4 v = __ldg(a4 + ch);
            mA |= (unsigned)(v.x <= 0.5f) << (4 * ch + 0);
            mA |= (unsigned)(v.y <= 0.5f) << (4 * ch + 1);
            mA |= (unsigned)(v.z <= 0.5f) << (4 * ch + 2);
            mA |= (unsigned)(v.w <= 0.5f) << (4 * ch + 3);
        }
    }
    if (y < H_N - 1) {
        const float4* b4 = reinterpret_cast<const float4*>(tgt + base + W_N);
#pragma unroll
        for (int ch = 0; ch < 4; ch++) {
            float4 v = __ldg(b4 + ch);
            mB |= (unsigned)(v.x <= 0.5f) << (4 * ch + 0);
            mB |= (unsigned)(v.y <= 0.5f) << (4 * ch + 1);
            mB |= (unsigned)(v.z <= 0.5f) << (4 * ch + 2);
            mB |= (unsigned)(v.w <= 0.5f) << (4 * ch + 3);
        }
    }

    // Combined "background anywhere in the 3-row band" mask per column.
    // For a foreground center pixel its own mC bit is 0, so including the
    // center column in the window is harmless.
    unsigned M = mA | mB | mC;

    // Horizontal halo across lanes via shuffle (image edges -> no background).
    unsigned left  = __shfl_up_sync(0xffffffffu, M, 1);
    unsigned right = __shfl_down_sync(0xffffffffu, M, 1);
    if (lane == 0)  left  = 0u;
    if (lane == 31) right = 0u;
    // bits [1..16] = local cols 0..15, bit 0 = col -1, bit 17 = col 16
    unsigned mExt = (M << 1) | ((left >> 15) & 1u) | ((right & 1u) << 17);

    // ---- Pass 2: BCE with weights ----
    const float4* p4 = reinterpret_cast<const float4*>(pred + base);
    float acc = 0.0f;
#pragma unroll
    for (int ch = 0; ch < 4; ch++) {
        float4 p = __ldg(p4 + ch);
        float pv[4] = {p.x, p.y, p.z, p.w};
#pragma unroll
        for (int k = 0; k < 4; k++) {
            const int i = 4 * ch + k;
            const float t  = ct[i];
            const float lp = fmaxf(__logf(pv[k]),        -100.0f);
            const float lq = fmaxf(__logf(1.0f - pv[k]), -100.0f);
            const float bce = -(t * lp + (1.0f - t) * lq);
            const bool fg   = (t > 0.5f);
            const bool thin = fg && (((mExt >> i) & 7u) != 0u);
            acc += thin ? 3.0f * bce : bce;
        }
    }

    // ---- Reduction: warp -> block -> g_partial[blockIdx.x] ----
#pragma unroll
    for (int off = 16; off > 0; off >>= 1)
        acc += __shfl_xor_sync(0xffffffffu, acc, off);

    __shared__ float ws[WARPS_PER_BLOCK];
    if (lane == 0) ws[warp_in_blk] = acc;
    __syncthreads();
    if (threadIdx.x == 0) {
        float s = 0.0f;
#pragma unroll
        for (int i = 0; i < WARPS_PER_BLOCK; i++) s += ws[i];
        g_partial[blockIdx.x] = s;  // overwritten every call: no zeroing needed
    }
}

// Single-block finalize: sum 256 partials in double, write the mean.
__global__ void __launch_bounds__(NBLOCKS)
tv_final(float* __restrict__ out) {
    double v = (double)g_partial[threadIdx.x];
#pragma unroll
    for (int off = 16; off > 0; off >>= 1)
        v += __shfl_xor_sync(0xffffffffu, v, off);

    __shared__ double ws[NBLOCKS / 32];
    const int lane = threadIdx.x & 31;
    const int wid  = threadIdx.x >> 5;
    if (lane == 0) ws[wid] = v;
    __syncthreads();
    if (threadIdx.x == 0) {
        double s = 0.0;
#pragma unroll
        for (int i = 0; i < NBLOCKS / 32; i++) s += ws[i];
        out[0] = (float)(s / (double)NPIX);
    }
}

extern "C" void kernel_launch(void* const* d_in, const int* in_sizes, int n_in,
                              void* d_out, int out_size) {
    const float* pred = (const float*)d_in[0];
    const float* tgt  = (const float*)d_in[1];
    float* out = (float*)d_out;
    (void)in_sizes; (void)n_in; (void)out_size;

    tv_main<<<NBLOCKS, WARPS_PER_BLOCK * 32>>>(pred, tgt);
    tv_final<<<1, NBLOCKS>>>(out);
}

// round 2
// speedup vs baseline: 1.2325x; 1.2325x over previous
#include <cuda_runtime.h>

// ThinVesselLoss: EDT only matters through thin = (0 < 2*dist < 3)
// <=> D2 in {1,2} <=> foreground pixel with >=1 in-bounds 8-neighbor
// background pixel. So: 3x3 stencil on (target > 0.5) + weighted BCE + mean.
//
// Single fused kernel: per-block partials + threadfence ticket; the last
// block reduces the 256 partials and writes the mean (then resets the
// ticket so every graph replay is identical).

#define B_N 4
#define H_N 512
#define W_N 512
#define NPIX (B_N * H_N * W_N)
#define ROWS_PER_BLOCK 8
#define NBLOCKS ((B_N * H_N) / ROWS_PER_BLOCK)   // 256
#define NTHREADS (ROWS_PER_BLOCK * 32)           // 256

__device__ float g_partial[NBLOCKS];
__device__ unsigned g_ticket;   // zero-initialized; last block resets to 0

__device__ __forceinline__ unsigned bg_mask_row(const float* __restrict__ tgt,
                                                long rowbase) {
    // 16 pixels per lane -> 16-bit background mask
    const float4* r4 = reinterpret_cast<const float4*>(tgt + rowbase);
    unsigned m = 0u;
#pragma unroll
    for (int ch = 0; ch < 4; ch++) {
        float4 v = __ldg(r4 + ch);
        m |= (unsigned)(v.x <= 0.5f) << (4 * ch + 0);
        m |= (unsigned)(v.y <= 0.5f) << (4 * ch + 1);
        m |= (unsigned)(v.z <= 0.5f) << (4 * ch + 2);
        m |= (unsigned)(v.w <= 0.5f) << (4 * ch + 3);
    }
    return m;
}

__global__ void __launch_bounds__(NTHREADS)
tv_fused(const float* __restrict__ pred, const float* __restrict__ tgt,
         float* __restrict__ out) {
    const int w    = threadIdx.x >> 5;   // warp in block = row in tile
    const int lane = threadIdx.x & 31;
    const int b    = blockIdx.x >> 6;              // image index (64 blocks/img)
    const int r0   = (blockIdx.x & 63) * ROWS_PER_BLOCK;
    const int y    = r0 + w;
    const long imgbase = (long)b * (H_N * W_N);
    const long base    = imgbase + (long)y * W_N + lane * 16;

    // ---- own-row: load target values + background mask ----
    float ct[16];
    unsigned mC = 0u;
    {
        const float4* c4 = reinterpret_cast<const float4*>(tgt + base);
#pragma unroll
        for (int ch = 0; ch < 4; ch++) {
            float4 v = __ldg(c4 + ch);
            ct[4 * ch + 0] = v.x; ct[4 * ch + 1] = v.y;
            ct[4 * ch + 2] = v.z; ct[4 * ch + 3] = v.w;
            mC |= (unsigned)(v.x <= 0.5f) << (4 * ch + 0);
            mC |= (unsigned)(v.y <= 0.5f) << (4 * ch + 1);
            mC |= (unsigned)(v.z <= 0.5f) << (4 * ch + 2);
            mC |= (unsigned)(v.w <= 0.5f) << (4 * ch + 3);
        }
    }

    // ---- publish masks: rows r0-1 .. r0+8 live in smask[0..9] ----
    __shared__ unsigned smask[ROWS_PER_BLOCK + 2][32];
    smask[w + 1][lane] = mC;
    if (w == 0) {
        unsigned m = 0u;
        if (r0 > 0) m = bg_mask_row(tgt, imgbase + (long)(r0 - 1) * W_N + lane * 16);
        smask[0][lane] = m;
    }
    if (w == ROWS_PER_BLOCK - 1) {
        unsigned m = 0u;
        if (r0 + ROWS_PER_BLOCK < H_N)
            m = bg_mask_row(tgt, imgbase + (long)(r0 + ROWS_PER_BLOCK) * W_N + lane * 16);
        smask[ROWS_PER_BLOCK + 1][lane] = m;
    }
    __syncthreads();

    // 3-row band OR (center col's own bit is 0 for fg pixels -> harmless)
    unsigned M = smask[w][lane] | smask[w + 1][lane] | smask[w + 2][lane];

    // horizontal halo via shuffle; image edges contribute no background
    unsigned left  = __shfl_up_sync(0xffffffffu, M, 1);
    unsigned right = __shfl_down_sync(0xffffffffu, M, 1);
    if (lane == 0)  left  = 0u;
    if (lane == 31) right = 0u;
    unsigned mExt = (M << 1) | ((left >> 15) & 1u) | ((right & 1u) << 17);

    // ---- weighted BCE ----
    const float4* p4 = reinterpret_cast<const float4*>(pred + base);
    float acc = 0.0f;
#pragma unroll
    for (int ch = 0; ch < 4; ch++) {
        float4 p = __ldg(p4 + ch);
        float pv[4] = {p.x, p.y, p.z, p.w};
#pragma unroll
        for (int k = 0; k < 4; k++) {
            const int i = 4 * ch + k;
            const float t  = ct[i];
            const float lp = fmaxf(__logf(pv[k]),        -100.0f);
            const float lq = fmaxf(__logf(1.0f - pv[k]), -100.0f);
            const float bce = -(t * lp + (1.0f - t) * lq);
            const bool thin = (t > 0.5f) && (((mExt >> i) & 7u) != 0u);
            acc += thin ? 3.0f * bce : bce;
        }
    }

    // ---- block reduction ----
#pragma unroll
    for (int off = 16; off > 0; off >>= 1)
        acc += __shfl_xor_sync(0xffffffffu, acc, off);

    __shared__ float ws[ROWS_PER_BLOCK];
    __shared__ bool amLast;
    if (lane == 0) ws[w] = acc;
    __syncthreads();
    if (threadIdx.x == 0) {
        float s = 0.0f;
#pragma unroll
        for (int i = 0; i < ROWS_PER_BLOCK; i++) s += ws[i];
        g_partial[blockIdx.x] = s;
        __threadfence();
        unsigned t = atomicAdd(&g_ticket, 1u);
        amLast = (t == (unsigned)(gridDim.x - 1));
    }
    __syncthreads();

    // ---- last block: final reduction over 256 partials (NTHREADS == NBLOCKS) ----
    if (amLast) {
        double v = (double)__ldcg(&g_partial[threadIdx.x]);  // L1-bypass read
#pragma unroll
        for (int off = 16; off > 0; off >>= 1)
            v += __shfl_xor_sync(0xffffffffu, v, off);
        __shared__ double ds[NTHREADS / 32];
        if (lane == 0) ds[w] = v;
        __syncthreads();
        if (threadIdx.x == 0) {
            double s = 0.0;
#pragma unroll
            for (int i = 0; i < NTHREADS / 32; i++) s += ds[i];
            out[0] = (float)(s / (double)NPIX);
            g_ticket = 0u;  // reset for the next (graph-replayed) call
        }
    }
}

extern "C" void kernel_launch(void* const* d_in, const int* in_sizes, int n_in,
                              void* d_out, int out_size) {
    const float* pred = (const float*)d_in[0];
    const float* tgt  = (const float*)d_in[1];
    float* out = (float*)d_out;
    (void)in_sizes; (void)n_in; (void)out_size;

    tv_fused<<<NBLOCKS, NTHREADS>>>(pred, tgt, out);
}